// round 8
// baseline (speedup 1.0000x reference)
#include <cuda_runtime.h>
#include <cstdint>

#define LOG2E_F 1.44269504088896340736f

constexpr int Bz = 2, SQ = 2048, SKV = 2048, HQ = 16, HKV = 4, DH = 128;
constexpr int BR = 128, BC = 64, NT = 256;

// smem float strides/offsets (double-buffered K and V^T)
constexpr int QSTR = 136;   // Q: pair-interleave, float2 loads
constexpr int KSTR = 144;   // K: 16-interleave, float4 loads (144 mod 32 = 16)
constexpr int VTSTR = 80;   // V^T: 16-interleave, float4 loads (80 mod 32 = 16)
constexpr int F_Q  = 0;                    // 128*136 = 17408
constexpr int F_K0 = 17408;                // 64*144  = 9216
constexpr int F_K1 = F_K0 + 9216;
constexpr int F_V0 = F_K1 + 9216;          // 128*80  = 10240
constexpr int F_V1 = F_V0 + 10240;
constexpr int F_TOT = F_V1 + 10240;        // 56320 floats
constexpr size_t SMEM_BYTES = (size_t)F_TOT * 4;   // 225280 B (1 CTA/SM)

// packed K: [b][hk][tile64][kv(64)][144]  16-interleaved k, tf32
__device__ float g_kc[(size_t)Bz * HKV * (SKV / BC) * BC * KSTR];
// packed V^T: [b][hk][tile64][d(128)][80]  16-interleaved kv, tf32
__device__ float g_vtc[(size_t)Bz * HKV * (SKV / BC) * DH * VTSTR];

// ---------------- helpers ----------------
__device__ __forceinline__ float tf32r(float x) {
    unsigned u;
    asm("cvt.rna.tf32.f32 %0, %1;" : "=r"(u) : "f"(x));
    return __uint_as_float(u);
}
__device__ __forceinline__ float ex2f(float x) {
    float y;
    asm("ex2.approx.f32 %0, %1;" : "=f"(y) : "f"(x));
    return y;
}
__device__ __forceinline__ uint32_t smem_u32(const void* p) {
    uint32_t a;
    asm("{ .reg .u64 t; cvta.to.shared.u64 t, %1; cvt.u32.u64 %0, t; }"
        : "=r"(a) : "l"(p));
    return a;
}
__device__ __forceinline__ void cpa16(uint32_t dst, const float* src) {
    asm volatile("cp.async.cg.shared.global [%0], [%1], 16;"
                 :: "r"(dst), "l"(src));
}
__device__ __forceinline__ void cpa_commit() {
    asm volatile("cp.async.commit_group;" ::: "memory");
}
__device__ __forceinline__ void cpa_wait1() {
    asm volatile("cp.async.wait_group 1;" ::: "memory");
}
// m16n8k8 row.col tf32 mma.  a0=aL.x a1=aH.x a2=aL.y a3=aH.y
__device__ __forceinline__ void mma8(float* c, float2 aL, float2 aH, float2 b) {
    unsigned a0 = __float_as_uint(aL.x), a1 = __float_as_uint(aH.x);
    unsigned a2 = __float_as_uint(aL.y), a3 = __float_as_uint(aH.y);
    unsigned b0 = __float_as_uint(b.x),  b1 = __float_as_uint(b.y);
    asm volatile(
        "mma.sync.aligned.m16n8k8.row.col.f32.tf32.tf32.f32 "
        "{%0,%1,%2,%3}, {%4,%5,%6,%7}, {%8,%9}, {%0,%1,%2,%3};\n"
        : "+f"(c[0]), "+f"(c[1]), "+f"(c[2]), "+f"(c[3])
        : "r"(a0), "r"(a1), "r"(a2), "r"(a3), "r"(b0), "r"(b1));
}

// ---------------- prepass: K pack (16-wide k interleave) ----------------
// per 16-block layout: pos 4*q + {0,1,2,3} = logical k {q, q+4, q+8, q+12}
__global__ void kprep_kernel(const float* __restrict__ k) {
    int idx = blockIdx.x * 256 + threadIdx.x;     // one float4 each
    int d  = (idx & 31) * 4;                      // d % 4 == 0
    int t  = idx >> 5;
    int hk = t & 3;  t >>= 2;
    int s  = t & (SKV - 1);
    int b  = t >> 11;
    float4 v4 = *(const float4*)(k + (((size_t)b * SKV + s) * HKV + hk) * DH + d);
    float* dst = g_kc + (((size_t)(b * HKV + hk) * (SKV / BC) + (s >> 6)) * BC
                         + (s & 63)) * KSTR;
    // pos(k) = (k&~15) + 4*(k&3) + 2*((k>>3)&1) + ((k>>2)&1); here k&3==0 base
    int g = (d & ~15) + 2 * ((d >> 3) & 1) + ((d >> 2) & 1);
    dst[g + 0]  = tf32r(v4.x);
    dst[g + 4]  = tf32r(v4.y);
    dst[g + 8]  = tf32r(v4.z);
    dst[g + 12] = tf32r(v4.w);
}

// ---------------- prepass: V transpose+pack (16-wide kv interleave) --------
// per 16-block: pos 4*q + {0,1,2,3} = kv {2q, 2q+1, 8+2q, 8+2q+1}
__device__ __forceinline__ int vperm16(int kv) {
    return (kv & ~15) + 4 * ((kv >> 1) & 3) + (kv & 1) + 2 * ((kv >> 3) & 1);
}
__global__ void vtprep_kernel(const float* __restrict__ v) {
    __shared__ float t[64][33];
    const int kvt = blockIdx.x;          // kv tile (64 wide)
    const int d0  = blockIdx.y * 32;
    const int bh  = blockIdx.z;          // b*HKV+hk
    const int b = bh >> 2, hk = bh & 3;
    const int tx = threadIdx.x, ty = threadIdx.y;   // 32 x 8
    const float* src = v + ((size_t)b * SKV * HKV + hk) * DH + d0;
    #pragma unroll
    for (int i = 0; i < 8; ++i) {
        int kvl = ty + 8 * i;
        t[kvl][tx] = src[(size_t)(kvt * 64 + kvl) * (HKV * DH) + tx];
    }
    __syncthreads();
    float* dst = g_vtc + ((size_t)bh * (SKV / BC) + kvt) * (DH * VTSTR)
               + (size_t)d0 * VTSTR;
    #pragma unroll
    for (int i = 0; i < 8; ++i) {
        int e = i * 256 + ty * 32 + tx;
        int dl = e >> 6, kvl = e & 63;
        dst[dl * VTSTR + vperm16(kvl)] = tf32r(t[kvl][dl]);
    }
}

// ---------------- main attention kernel ----------------
__global__ void __launch_bounds__(NT, 1)
fa_kernel(const float* __restrict__ q,
          const float* __restrict__ mask,
          float* __restrict__ out)
{
    extern __shared__ float sm[];
    const uint32_t sb = smem_u32(sm);

    const int tid = threadIdx.x;
    const int w = tid >> 5;            // 8 warps, warp owns rows w*16..w*16+15
    const int lane = tid & 31;
    const int qgrp = lane >> 2;
    const int qid  = lane & 3;

    const int bx = (int)gridDim.x - 1 - (int)blockIdx.x;   // big-first order
    const int q0 = bx * BR;
    const int h  = blockIdx.y;
    const int b  = blockIdx.z;
    const int hk = h & (HKV - 1);
    const int bh = b * HKV + hk;
    const int ntiles = 2 * bx + 2;

    const uint32_t KB[2] = { sb + F_K0 * 4u, sb + F_K1 * 4u };
    const uint32_t VB[2] = { sb + F_V0 * 4u, sb + F_V1 * 4u };
    const float* kc0 = g_kc + (size_t)bh * (SKV / BC) * (BC * KSTR);
    const float* vc0 = g_vtc + (size_t)bh * (SKV / BC) * (DH * VTSTR);

    // ---- prologue: prefetch tiles 0 and 1 (two cp.async groups) ----
    #pragma unroll
    for (int tpre = 0; tpre < 2; ++tpre) {
        const float* ks = kc0 + (size_t)tpre * (BC * KSTR);
        const float* vs = vc0 + (size_t)tpre * (DH * VTSTR);
        #pragma unroll
        for (int i = 0; i < 10; ++i) {
            int idx = tid + NT * i;
            if (idx < BC * KSTR / 4)  cpa16(KB[tpre] + idx * 16, ks + idx * 4);
            if (idx < DH * VTSTR / 4) cpa16(VB[tpre] + idx * 16, vs + idx * 4);
        }
        cpa_commit();
    }

    // ---- Q tile: LDG + scale + tf32 + pair-interleaved STS ----
    {
        const float qscale = LOG2E_F * 0.08838834764831845f;  // log2e/sqrt(128)
        const float* qb = q + (((size_t)b * SQ + q0) * HQ + h) * DH;
        #pragma unroll
        for (int i = 0; i < 16; ++i) {
            int f4 = tid + NT * i;
            int row = f4 >> 5;
            int c = (f4 & 31) << 2;
            float4 v4 = *(const float4*)(qb + (size_t)row * (HQ * DH) + c);
            int g = (c & ~7) + ((c & 4) ? 1 : 0);
            float* dst = sm + F_Q + row * QSTR;
            dst[g + 0] = tf32r(v4.x * qscale);
            dst[g + 2] = tf32r(v4.y * qscale);
            dst[g + 4] = tf32r(v4.z * qscale);
            dst[g + 6] = tf32r(v4.w * qscale);
        }
    }

    const int rg0 = q0 + w * 16 + qgrp;      // global row (and rg0+8)
    const int rwmax = q0 + w * 16 + 15;      // causal warp bound
    const float* mrow0 = mask + ((size_t)(b * HQ + h) * SQ + rg0) * SKV;
    const float* mrow1 = mrow0 + (size_t)8 * SKV;
    const float* qrow0 = sm + F_Q + (w * 16 + qgrp) * QSTR;
    const float* qrow1 = qrow0 + 8 * QSTR;

    float O[16][4];
    #pragma unroll
    for (int nt = 0; nt < 16; ++nt) {
        O[nt][0] = 0.f; O[nt][1] = 0.f; O[nt][2] = 0.f; O[nt][3] = 0.f;
    }
    float ls0 = 0.f, ls1 = 0.f;

    for (int j = 0; j < ntiles; ++j) {
        const int kv0 = j * BC;
        const int cur = j & 1;

        cpa_wait1();                    // tile j resident (j+1 may be in flight)
        __syncthreads();                // all threads' copies of tile j visible

        if (kv0 <= rwmax) {
            // ---- mask prefetch into registers (hidden under MMA1) ----
            float2 mk0[8], mk1[8];
            #pragma unroll
            for (int nt = 0; nt < 8; ++nt) {
                mk0[nt] = *(const float2*)(mrow0 + kv0 + nt * 8 + 2 * qid);
                mk1[nt] = *(const float2*)(mrow1 + kv0 + nt * 8 + 2 * qid);
            }

            // ---- MMA1: S(m16 x n64) = Q @ K^T, K via float4 (2 steps) ----
            float S[8][4];
            #pragma unroll
            for (int nt = 0; nt < 8; ++nt) {
                S[nt][0] = 0.f; S[nt][1] = 0.f; S[nt][2] = 0.f; S[nt][3] = 0.f;
            }
            {
                const float* Ks = sm + (cur ? F_K1 : F_K0);
                #pragma unroll
                for (int t = 0; t < 8; ++t) {          // 16-blocks of k
                    const int ko0 = (2 * t) * 8 + 2 * qid;
                    const int ko1 = ko0 + 8;
                    float2 aL0 = *(const float2*)(qrow0 + ko0);
                    float2 aH0 = *(const float2*)(qrow1 + ko0);
                    float2 aL1 = *(const float2*)(qrow0 + ko1);
                    float2 aH1 = *(const float2*)(qrow1 + ko1);
                    #pragma unroll
                    for (int nt = 0; nt < 8; ++nt) {
                        float4 kb = *(const float4*)(Ks + (nt * 8 + qgrp) * KSTR
                                                     + t * 16 + 4 * qid);
                        mma8(S[nt], aL0, aH0, make_float2(kb.x, kb.y));
                        mma8(S[nt], aL1, aH1, make_float2(kb.z, kb.w));
                    }
                }
            }

            // ---- softmax: P = exp2(S + mask*log2e), causal-zeroed, in regs ----
            #pragma unroll
            for (int nt = 0; nt < 8; ++nt) {
                const int c0 = kv0 + nt * 8 + 2 * qid;
                float p00 = (c0     <= rg0)     ? ex2f(S[nt][0] + LOG2E_F * mk0[nt].x) : 0.f;
                float p01 = (c0 + 1 <= rg0)     ? ex2f(S[nt][1] + LOG2E_F * mk0[nt].y) : 0.f;
                float p10 = (c0     <= rg0 + 8) ? ex2f(S[nt][2] + LOG2E_F * mk1[nt].x) : 0.f;
                float p11 = (c0 + 1 <= rg0 + 8) ? ex2f(S[nt][3] + LOG2E_F * mk1[nt].y) : 0.f;
                ls0 += p00 + p01;
                ls1 += p10 + p11;
                S[nt][0] = tf32r(p00);
                S[nt][1] = tf32r(p01);
                S[nt][2] = tf32r(p10);
                S[nt][3] = tf32r(p11);
            }

            // ---- MMA2: O(m16 x d128) += P @ V, P from regs, V via float4 ----
            {
                const float* Vs = sm + (cur ? F_V1 : F_V0);
                #pragma unroll
                for (int t = 0; t < 4; ++t) {          // 16-blocks of kv
                    float2 aL0 = make_float2(S[2 * t][0],     S[2 * t][1]);
                    float2 aH0 = make_float2(S[2 * t][2],     S[2 * t][3]);
                    float2 aL1 = make_float2(S[2 * t + 1][0], S[2 * t + 1][1]);
                    float2 aH1 = make_float2(S[2 * t + 1][2], S[2 * t + 1][3]);
                    #pragma unroll
                    for (int nt = 0; nt < 16; ++nt) {
                        float4 vb = *(const float4*)(Vs + (nt * 8 + qgrp) * VTSTR
                                                     + t * 16 + 4 * qid);
                        mma8(O[nt], aL0, aH0, make_float2(vb.x, vb.y));
                        mma8(O[nt], aL1, aH1, make_float2(vb.z, vb.w));
                    }
                }
            }
        }

        __syncthreads();                // all warps done with buffer `cur`
        if (j + 2 < ntiles) {
            const float* ks = kc0 + (size_t)(j + 2) * (BC * KSTR);
            const float* vs = vc0 + (size_t)(j + 2) * (DH * VTSTR);
            #pragma unroll
            for (int i = 0; i < 10; ++i) {
                int idx = tid + NT * i;
                if (idx < BC * KSTR / 4)  cpa16(KB[cur] + idx * 16, ks + idx * 4);
                if (idx < DH * VTSTR / 4) cpa16(VB[cur] + idx * 16, vs + idx * 4);
            }
        }
        cpa_commit();                   // commit (possibly empty) group
    }

    // ---- row sums (reduce over qid lanes), normalize, store ----
    ls0 += __shfl_xor_sync(0xffffffffu, ls0, 1);
    ls0 += __shfl_xor_sync(0xffffffffu, ls0, 2);
    ls1 += __shfl_xor_sync(0xffffffffu, ls1, 1);
    ls1 += __shfl_xor_sync(0xffffffffu, ls1, 2);
    const float inv0 = 1.0f / ls0;
    const float inv1 = 1.0f / ls1;

    float* o0 = out + (((size_t)b * SQ + rg0) * HQ + h) * DH;
    float* o1 = o0 + (size_t)8 * HQ * DH;
    #pragma unroll
    for (int nt = 0; nt < 16; ++nt) {
        const int c = nt * 8 + 2 * qid;
        *(float2*)(o0 + c) = make_float2(O[nt][0] * inv0, O[nt][1] * inv0);
        *(float2*)(o1 + c) = make_float2(O[nt][2] * inv1, O[nt][3] * inv1);
    }
}

extern "C" void kernel_launch(void* const* d_in, const int* in_sizes, int n_in,
                              void* d_out, int out_size) {
    (void)in_sizes; (void)n_in; (void)out_size;
    const float* q = (const float*)d_in[0];
    const float* k = (const float*)d_in[1];
    const float* v = (const float*)d_in[2];
    const float* mask = (const float*)d_in[3];
    float* out = (float*)d_out;

    cudaFuncSetAttribute(fa_kernel,
                         cudaFuncAttributeMaxDynamicSharedMemorySize,
                         (int)SMEM_BYTES);

    kprep_kernel<<<(Bz * SKV * HKV * DH / 4) / 256, 256>>>(k);
    vtprep_kernel<<<dim3(SKV / BC, DH / 32, Bz * HKV), dim3(32, 8)>>>(v);
    fa_kernel<<<dim3(SQ / BR, HQ, Bz), NT, SMEM_BYTES>>>(q, mask, out);
}

// round 9
// speedup vs baseline: 1.0797x; 1.0797x over previous
#include <cuda_runtime.h>
#include <cstdint>

#define LOG2E_F 1.44269504088896340736f

constexpr int Bz = 2, SQ = 2048, SKV = 2048, HQ = 16, HKV = 4, DH = 128;
constexpr int BR = 128, BC = 64, NT = 256;

// smem float offsets (double-buffered K and V^T)
constexpr int QSTR = 136, KSTR = 136, VTSTR = 72;
constexpr int F_Q  = 0;                  // 128*136 = 17408
constexpr int F_K0 = 17408;              // 64*136  = 8704
constexpr int F_K1 = F_K0 + 8704;
constexpr int F_V0 = F_K1 + 8704;        // 128*72  = 9216
constexpr int F_V1 = F_V0 + 9216;
constexpr int F_TOT = F_V1 + 9216;       // 53248 floats
constexpr size_t SMEM_BYTES = (size_t)F_TOT * 4;   // 212992 B (1 CTA/SM)

// packed K: [b][hk][tile64][kv(64)][136] tf32, k-pair interleaved for fragments
__device__ float g_kc[(size_t)Bz * HKV * (SKV / BC) * BC * KSTR];
// packed V^T: [b][hk][tile64][d(128)][72] tf32, kv contiguous (NO perm)
__device__ float g_vtc[(size_t)Bz * HKV * (SKV / BC) * DH * VTSTR];

// ---------------- helpers ----------------
__device__ __forceinline__ float tf32r(float x) {
    unsigned u;
    asm("cvt.rna.tf32.f32 %0, %1;" : "=r"(u) : "f"(x));
    return __uint_as_float(u);
}
__device__ __forceinline__ float ex2f(float x) {
    float y;
    asm("ex2.approx.f32 %0, %1;" : "=f"(y) : "f"(x));
    return y;
}
__device__ __forceinline__ uint32_t smem_u32(const void* p) {
    uint32_t a;
    asm("{ .reg .u64 t; cvta.to.shared.u64 t, %1; cvt.u32.u64 %0, t; }"
        : "=r"(a) : "l"(p));
    return a;
}
__device__ __forceinline__ void cpa16(uint32_t dst, const float* src) {
    asm volatile("cp.async.cg.shared.global [%0], [%1], 16;"
                 :: "r"(dst), "l"(src));
}
__device__ __forceinline__ void cpa_commit() {
    asm volatile("cp.async.commit_group;" ::: "memory");
}
__device__ __forceinline__ void cpa_wait0() {
    asm volatile("cp.async.wait_group 0;" ::: "memory");
}
// m16n8k8 row.col tf32 mma.  a0=aL.x a1=aH.x a2=aL.y a3=aH.y
__device__ __forceinline__ void mma8(float* c, float2 aL, float2 aH, float2 b) {
    unsigned a0 = __float_as_uint(aL.x), a1 = __float_as_uint(aH.x);
    unsigned a2 = __float_as_uint(aL.y), a3 = __float_as_uint(aH.y);
    unsigned b0 = __float_as_uint(b.x),  b1 = __float_as_uint(b.y);
    asm volatile(
        "mma.sync.aligned.m16n8k8.row.col.f32.tf32.tf32.f32 "
        "{%0,%1,%2,%3}, {%4,%5,%6,%7}, {%8,%9}, {%0,%1,%2,%3};\n"
        : "+f"(c[0]), "+f"(c[1]), "+f"(c[2]), "+f"(c[3])
        : "r"(a0), "r"(a1), "r"(a2), "r"(a3), "r"(b0), "r"(b1));
}

// ---------------- prepass: K pack (fragment k-pair interleave) ----------------
__global__ void kprep_kernel(const float* __restrict__ k) {
    int idx = blockIdx.x * 256 + threadIdx.x;     // one float4 each
    int d  = (idx & 31) * 4;
    int t  = idx >> 5;
    int hk = t & 3;  t >>= 2;
    int s  = t & (SKV - 1);
    int b  = t >> 11;
    float4 v4 = *(const float4*)(k + (((size_t)b * SKV + s) * HKV + hk) * DH + d);
    float* dst = g_kc + (((size_t)(b * HKV + hk) * (SKV / BC) + (s >> 6)) * BC
                         + (s & 63)) * KSTR;
    int g = (d & ~7) + ((d & 4) ? 1 : 0);
    dst[g + 0] = tf32r(v4.x);
    dst[g + 2] = tf32r(v4.y);
    dst[g + 4] = tf32r(v4.z);
    dst[g + 6] = tf32r(v4.w);
}

// ---------------- prepass: V transpose+pack (plain kv order) ----------------
__global__ void vtprep_kernel(const float* __restrict__ v) {
    __shared__ float t[64][33];
    const int kvt = blockIdx.x;          // kv tile (64 wide)
    const int d0  = blockIdx.y * 32;
    const int bh  = blockIdx.z;          // b*HKV+hk
    const int b = bh >> 2, hk = bh & 3;
    const int tx = threadIdx.x, ty = threadIdx.y;   // 32 x 8
    const float* src = v + ((size_t)b * SKV * HKV + hk) * DH + d0;
    #pragma unroll
    for (int i = 0; i < 8; ++i) {
        int kvl = ty + 8 * i;
        t[kvl][tx] = src[(size_t)(kvt * 64 + kvl) * (HKV * DH) + tx];
    }
    __syncthreads();
    float* dst = g_vtc + ((size_t)bh * (SKV / BC) + kvt) * (DH * VTSTR)
               + (size_t)d0 * VTSTR;
    #pragma unroll
    for (int i = 0; i < 8; ++i) {
        int e = i * 256 + ty * 32 + tx;
        int dl = e >> 6, kvl = e & 63;
        dst[dl * VTSTR + kvl] = tf32r(t[kvl][dl]);
    }
}

// ---------------- main attention kernel ----------------
__global__ void __launch_bounds__(NT, 1)
fa_kernel(const float* __restrict__ q,
          const float* __restrict__ mask,
          float* __restrict__ out)
{
    extern __shared__ float sm[];
    const uint32_t sb = smem_u32(sm);

    const int tid = threadIdx.x;
    const int w = tid >> 5;            // 8 warps, warp owns rows w*16..w*16+15
    const int lane = tid & 31;
    const int qgrp = lane >> 2;
    const int qid  = lane & 3;

    const int bx = blockIdx.x;
    const int q0 = bx * BR;
    const int h  = blockIdx.y;
    const int b  = blockIdx.z;
    const int hk = h & (HKV - 1);
    const int bh = b * HKV + hk;
    const int ntiles = 2 * bx + 2;

    const uint32_t KB[2] = { sb + F_K0 * 4u, sb + F_K1 * 4u };
    const uint32_t VB[2] = { sb + F_V0 * 4u, sb + F_V1 * 4u };
    const float* kc0 = g_kc + (size_t)bh * (SKV / BC) * (BC * KSTR);
    const float* vc0 = g_vtc + (size_t)bh * (SKV / BC) * (DH * VTSTR);

    // ---- prologue: prefetch tile 0 into buffer 0 ----
    {
        const float* ks = kc0;
        const float* vs = vc0;
        #pragma unroll
        for (int i = 0; i < 9; ++i) {
            int idx = tid + NT * i;
            if (idx < BC * KSTR / 4)  cpa16(KB[0] + idx * 16, ks + idx * 4);
            if (idx < DH * VTSTR / 4) cpa16(VB[0] + idx * 16, vs + idx * 4);
        }
        cpa_commit();
    }

    // ---- Q tile: LDG + scale + tf32 + interleaved STS (overlaps prefetch) ----
    {
        const float qscale = LOG2E_F * 0.08838834764831845f;  // log2e/sqrt(128)
        const float* qb = q + (((size_t)b * SQ + q0) * HQ + h) * DH;
        #pragma unroll
        for (int i = 0; i < 16; ++i) {
            int f4 = tid + NT * i;
            int row = f4 >> 5;
            int c = (f4 & 31) << 2;
            float4 v4 = *(const float4*)(qb + (size_t)row * (HQ * DH) + c);
            int g = (c & ~7) + ((c & 4) ? 1 : 0);
            float* dst = sm + F_Q + row * QSTR;
            dst[g + 0] = tf32r(v4.x * qscale);
            dst[g + 2] = tf32r(v4.y * qscale);
            dst[g + 4] = tf32r(v4.z * qscale);
            dst[g + 6] = tf32r(v4.w * qscale);
        }
    }

    const int rg0 = q0 + w * 16 + qgrp;      // global row (and rg0+8)
    const int rwmax = q0 + w * 16 + 15;      // causal warp bound
    const float* mrow0 = mask + ((size_t)(b * HQ + h) * SQ + rg0) * SKV;
    const float* mrow1 = mrow0 + (size_t)8 * SKV;
    const float* qrow0 = sm + F_Q + (w * 16 + qgrp) * QSTR;
    const float* qrow1 = qrow0 + 8 * QSTR;

    float O[16][4];
    #pragma unroll
    for (int nt = 0; nt < 16; ++nt) {
        O[nt][0] = 0.f; O[nt][1] = 0.f; O[nt][2] = 0.f; O[nt][3] = 0.f;
    }
    float ls0 = 0.f, ls1 = 0.f;

    for (int j = 0; j < ntiles; ++j) {
        const int kv0 = j * BC;
        const int cur = j & 1, nxt = cur ^ 1;

        cpa_wait0();                    // tile j resident (sole group in flight)
        __syncthreads();                // publish tile j AND prove iter j-1 done
                                        // (buffer `nxt` was last read in j-1)

        // ---- prefetch tile j+1 into `nxt`; completes during this compute ----
        if (j + 1 < ntiles) {
            const float* ks = kc0 + (size_t)(j + 1) * (BC * KSTR);
            const float* vs = vc0 + (size_t)(j + 1) * (DH * VTSTR);
            #pragma unroll
            for (int i = 0; i < 9; ++i) {
                int idx = tid + NT * i;
                if (idx < BC * KSTR / 4)  cpa16(KB[nxt] + idx * 16, ks + idx * 4);
                if (idx < DH * VTSTR / 4) cpa16(VB[nxt] + idx * 16, vs + idx * 4);
            }
        }
        cpa_commit();                   // commit (possibly empty) group

        if (kv0 <= rwmax) {
            // ---- mask prefetch into registers (hidden under MMA1) ----
            float2 mk0[8], mk1[8];
            #pragma unroll
            for (int nt = 0; nt < 8; ++nt) {
                mk0[nt] = *(const float2*)(mrow0 + kv0 + nt * 8 + 2 * qid);
                mk1[nt] = *(const float2*)(mrow1 + kv0 + nt * 8 + 2 * qid);
            }

            // ---- MMA1: S(m16 x n64) = Q @ K^T ----
            float S[8][4];
            #pragma unroll
            for (int nt = 0; nt < 8; ++nt) {
                S[nt][0] = 0.f; S[nt][1] = 0.f; S[nt][2] = 0.f; S[nt][3] = 0.f;
            }
            {
                const float* Ks = sm + (cur ? F_K1 : F_K0);
                #pragma unroll
                for (int kt = 0; kt < 16; ++kt) {
                    const int ko = kt * 8 + 2 * qid;
                    float2 aL = *(const float2*)(qrow0 + ko);
                    float2 aH = *(const float2*)(qrow1 + ko);
                    #pragma unroll
                    for (int nt = 0; nt < 8; ++nt) {
                        float2 bb = *(const float2*)(Ks + (nt * 8 + qgrp) * KSTR + ko);
                        mma8(S[nt], aL, aH, bb);
                    }
                }
            }

            // ---- softmax: P = exp2(S + mask*log2e), causal-zeroed, in regs ----
            #pragma unroll
            for (int nt = 0; nt < 8; ++nt) {
                const int c0 = kv0 + nt * 8 + 2 * qid;
                float p00 = (c0     <= rg0)     ? ex2f(S[nt][0] + LOG2E_F * mk0[nt].x) : 0.f;
                float p01 = (c0 + 1 <= rg0)     ? ex2f(S[nt][1] + LOG2E_F * mk0[nt].y) : 0.f;
                float p10 = (c0     <= rg0 + 8) ? ex2f(S[nt][2] + LOG2E_F * mk1[nt].x) : 0.f;
                float p11 = (c0 + 1 <= rg0 + 8) ? ex2f(S[nt][3] + LOG2E_F * mk1[nt].y) : 0.f;
                ls0 += p00 + p01;
                ls1 += p10 + p11;
                S[nt][0] = tf32r(p00);
                S[nt][1] = tf32r(p01);
                S[nt][2] = tf32r(p10);
                S[nt][3] = tf32r(p11);
            }

            // ---- MMA2: O(m16 x d128) += P @ V, P straight from registers ----
            {
                const float* Vs = sm + (cur ? F_V1 : F_V0);
                #pragma unroll
                for (int kt = 0; kt < 8; ++kt) {
                    float2 aL = make_float2(S[kt][0], S[kt][1]);
                    float2 aH = make_float2(S[kt][2], S[kt][3]);
                    #pragma unroll
                    for (int nt = 0; nt < 16; ++nt) {
                        float2 bb = *(const float2*)(Vs + (nt * 8 + qgrp) * VTSTR
                                                     + kt * 8 + 2 * qid);
                        mma8(O[nt], aL, aH, bb);
                    }
                }
            }
        }
    }

    // ---- row sums (reduce over qid lanes), normalize, store ----
    ls0 += __shfl_xor_sync(0xffffffffu, ls0, 1);
    ls0 += __shfl_xor_sync(0xffffffffu, ls0, 2);
    ls1 += __shfl_xor_sync(0xffffffffu, ls1, 1);
    ls1 += __shfl_xor_sync(0xffffffffu, ls1, 2);
    const float inv0 = 1.0f / ls0;
    const float inv1 = 1.0f / ls1;

    float* o0 = out + (((size_t)b * SQ + rg0) * HQ + h) * DH;
    float* o1 = o0 + (size_t)8 * HQ * DH;
    #pragma unroll
    for (int nt = 0; nt < 16; ++nt) {
        const int c = nt * 8 + 2 * qid;
        *(float2*)(o0 + c) = make_float2(O[nt][0] * inv0, O[nt][1] * inv0);
        *(float2*)(o1 + c) = make_float2(O[nt][2] * inv1, O[nt][3] * inv1);
    }
}

extern "C" void kernel_launch(void* const* d_in, const int* in_sizes, int n_in,
                              void* d_out, int out_size) {
    (void)in_sizes; (void)n_in; (void)out_size;
    const float* q = (const float*)d_in[0];
    const float* k = (const float*)d_in[1];
    const float* v = (const float*)d_in[2];
    const float* mask = (const float*)d_in[3];
    float* out = (float*)d_out;

    cudaFuncSetAttribute(fa_kernel,
                         cudaFuncAttributeMaxDynamicSharedMemorySize,
                         (int)SMEM_BYTES);

    kprep_kernel<<<(Bz * SKV * HKV * DH / 4) / 256, 256>>>(k);
    vtprep_kernel<<<dim3(SKV / BC, DH / 32, Bz * HKV), dim3(32, 8)>>>(v);
    fa_kernel<<<dim3(SQ / BR, HQ, Bz), NT, SMEM_BYTES>>>(q, mask, out);
}